// round 1
// baseline (speedup 1.0000x reference)
#include <cuda_runtime.h>
#include <cstdint>

// Problem constants
#define NCH    24          // B*C = 8*3 channels
#define CHPX   (1 << 20)   // pixels per channel (1024*1024)
#define NBINS  256

// Scratch (static device globals — no allocation allowed)
__device__ unsigned int g_hist[2 * NCH * NBINS];     // [0..23]=dst, [24..47]=ref
__device__ float        g_table[NCH * NBINS];        // table value already /255
__device__ unsigned char g_pix[(size_t)NCH * CHPX];  // cached per-pixel LUT index

// ---------------------------------------------------------------------------
// K0: zero the histograms (required every graph replay)
// ---------------------------------------------------------------------------
__global__ void k_zero_hist() {
    int i = blockIdx.x * blockDim.x + threadIdx.x;
    if (i < 2 * NCH * NBINS) g_hist[i] = 0u;
}

// ---------------------------------------------------------------------------
// K1: histograms of dst (ch 0..23) and ref (ch 24..47).
// For dst channels also store the 8-bit pixel index used by the final gather.
// blockIdx.y = channel id (0..47), blockIdx.x strided over the channel.
// ---------------------------------------------------------------------------
__global__ void k_hist(const float* __restrict__ dst,
                       const float* __restrict__ ref) {
    const int ch = blockIdx.y;
    const bool is_dst = ch < NCH;
    const float* __restrict__ src =
        is_dst ? dst + (size_t)ch * CHPX : ref + (size_t)(ch - NCH) * CHPX;

    __shared__ unsigned int sh[NBINS];
    for (int i = threadIdx.x; i < NBINS; i += blockDim.x) sh[i] = 0u;
    __syncthreads();

    const float4* __restrict__ s4 = reinterpret_cast<const float4*>(src);
    uchar4* __restrict__ p4 =
        is_dst ? reinterpret_cast<uchar4*>(g_pix) + (size_t)ch * (CHPX / 4)
               : nullptr;

    const float scale = 256.0f / 255.0f;  // matches BINS/255.0 rounded to f32
    const int n4 = CHPX / 4;
    const int stride = gridDim.x * blockDim.x;

    for (int i = blockIdx.x * blockDim.x + threadIdx.x; i < n4; i += stride) {
        float4 v = s4[i];
        // img255 first (f32), then *scale (f32) — bit-faithful to reference order
        float t0 = v.x * 255.0f, t1 = v.y * 255.0f;
        float t2 = v.z * 255.0f, t3 = v.w * 255.0f;
        int i0 = min(max((int)(t0 * scale), 0), 255);
        int i1 = min(max((int)(t1 * scale), 0), 255);
        int i2 = min(max((int)(t2 * scale), 0), 255);
        int i3 = min(max((int)(t3 * scale), 0), 255);
        atomicAdd(&sh[i0], 1u);
        atomicAdd(&sh[i1], 1u);
        atomicAdd(&sh[i2], 1u);
        atomicAdd(&sh[i3], 1u);
        if (is_dst) {
            // pix = clip(trunc(x*255), 0, 255)
            uchar4 p;
            p.x = (unsigned char)min(max((int)t0, 0), 255);
            p.y = (unsigned char)min(max((int)t1, 0), 255);
            p.z = (unsigned char)min(max((int)t2, 0), 255);
            p.w = (unsigned char)min(max((int)t3, 0), 255);
            p4[i] = p;
        }
    }
    __syncthreads();
    for (int i = threadIdx.x; i < NBINS; i += blockDim.x) {
        unsigned int c = sh[i];
        if (c) atomicAdd(&g_hist[ch * NBINS + i], c);
    }
}

// ---------------------------------------------------------------------------
// K2: per-channel CDFs + transfer table. blockIdx.x = channel k (0..23).
// table[i] = first j in 1..255 with hr[j-1] <= hd[i] <= hr[j], else i;
// table[0]=0, table[255]=255. Stored pre-divided by 255.
// ---------------------------------------------------------------------------
__global__ void k_table() {
    const int k = blockIdx.x;
    __shared__ float cd[NBINS];
    __shared__ float cr[NBINS];
    const int t = threadIdx.x;  // 256 threads

    // counts sum to exactly 2^20 -> normalization is an exact pow2 multiply
    cd[t] = (float)g_hist[k * NBINS + t] * (1.0f / 1048576.0f);
    cr[t] = (float)g_hist[(NCH + k) * NBINS + t] * (1.0f / 1048576.0f);
    __syncthreads();

    if (t == 0) {  // sequential f32 cumsum, same order as reference
        float a = 0.0f, b = 0.0f;
        for (int i = 0; i < NBINS; i++) {
            a += cd[i]; cd[i] = a;
            b += cr[i]; cr[i] = b;
        }
    }
    __syncthreads();

    int val = t;
    if (t > 0 && t < NBINS - 1) {
        const float x = cd[t];
        #pragma unroll 8
        for (int j = 1; j < NBINS; j++) {
            if (cr[j - 1] <= x && x <= cr[j]) { val = j; break; }
        }
    }
    g_table[k * NBINS + t] = (float)val / 255.0f;
}

// ---------------------------------------------------------------------------
// K3: gather. out = table[bugged_channel][pix] (already /255).
// Bug-faithful mapping: channel (b,c) uses table[b*c].
// ---------------------------------------------------------------------------
__global__ void k_gather(float* __restrict__ out) {
    const int ch = blockIdx.y;          // 0..23 (flat b*3+c)
    const int b = ch / 3, c = ch % 3;
    const int k = b * c;                // bug-faithful table index

    __shared__ float lut[NBINS];
    if (threadIdx.x < NBINS) lut[threadIdx.x] = g_table[k * NBINS + threadIdx.x];
    __syncthreads();

    const uchar4* __restrict__ p4 =
        reinterpret_cast<const uchar4*>(g_pix) + (size_t)ch * (CHPX / 4);
    float4* __restrict__ o4 =
        reinterpret_cast<float4*>(out) + (size_t)ch * (CHPX / 4);

    const int n4 = CHPX / 4;
    const int stride = gridDim.x * blockDim.x;
    for (int i = blockIdx.x * blockDim.x + threadIdx.x; i < n4; i += stride) {
        uchar4 p = p4[i];
        o4[i] = make_float4(lut[p.x], lut[p.y], lut[p.z], lut[p.w]);
    }
}

// ---------------------------------------------------------------------------
extern "C" void kernel_launch(void* const* d_in, const int* in_sizes, int n_in,
                              void* d_out, int out_size) {
    const float* dst = (const float*)d_in[0];
    const float* ref = (const float*)d_in[1];
    float* out = (float*)d_out;

    k_zero_hist<<<(2 * NCH * NBINS + 255) / 256, 256>>>();
    k_hist<<<dim3(64, 2 * NCH), 256>>>(dst, ref);
    k_table<<<NCH, NBINS>>>();
    k_gather<<<dim3(128, NCH), 256>>>(out);
}

// round 2
// speedup vs baseline: 1.1296x; 1.1296x over previous
#include <cuda_runtime.h>
#include <cstdint>

// Problem constants
#define NCH    24          // B*C = 8*3 channels
#define CHPX   (1 << 20)   // pixels per channel (1024*1024)
#define NBINS  256
#define NWARP  8           // warps per hist block (256 threads)

// Scratch (static device globals — no allocation allowed)
__device__ unsigned int g_hist[2 * NCH * NBINS];     // [0..23]=dst, [24..47]=ref
__device__ float        g_table[NCH * NBINS];        // table value already /255
__device__ unsigned char g_pix[(size_t)NCH * CHPX];  // cached per-pixel LUT index

// Bug-faithful: reference reads table[b*c]; only these k are ever used.
__host__ __device__ __forceinline__ bool chan_used(int k) {
    return (k <= 8) || (k <= 14 && (k & 1) == 0);
}

// ---------------------------------------------------------------------------
// K0: zero the histograms (required every graph replay)
// ---------------------------------------------------------------------------
__global__ void k_zero_hist() {
    int i = blockIdx.x * blockDim.x + threadIdx.x;
    if (i < 2 * NCH * NBINS) g_hist[i] = 0u;
}

// ---------------------------------------------------------------------------
// K1: histograms of dst (ch 0..23) and ref (ch 24..47).
// dst channels always emit the 8-bit pixel index; histogram atomics only for
// channels whose table is actually consumed (bug-faithful table[b*c]).
// Unused ref channels exit without touching memory.
// Per-warp privatized sub-histograms kill inter-warp atomic contention.
// ---------------------------------------------------------------------------
__global__ void k_hist(const float* __restrict__ dst,
                       const float* __restrict__ ref) {
    const int ch = blockIdx.y;
    const bool is_dst = ch < NCH;
    const int k = is_dst ? ch : ch - NCH;
    const bool need_hist = chan_used(k);

    if (!is_dst && !need_hist) return;  // unused ref channel: nothing to do

    const float* __restrict__ src =
        is_dst ? dst + (size_t)k * CHPX : ref + (size_t)k * CHPX;

    __shared__ unsigned int sh[NWARP][NBINS];

    const int tid = threadIdx.x;
    const int wid = tid >> 5;

    if (need_hist) {
        #pragma unroll
        for (int w = 0; w < NWARP; w++)
            for (int i = tid; i < NBINS; i += blockDim.x) sh[w][i] = 0u;
        __syncthreads();
    }

    const float4* __restrict__ s4 = reinterpret_cast<const float4*>(src);
    uchar4* __restrict__ p4 =
        is_dst ? reinterpret_cast<uchar4*>(g_pix) + (size_t)k * (CHPX / 4)
               : nullptr;

    const float scale = 256.0f / 255.0f;  // f32(BINS/255.0)
    const int n4 = CHPX / 4;
    const int stride = gridDim.x * blockDim.x;

    unsigned int* __restrict__ myh = sh[wid];

    for (int i = blockIdx.x * blockDim.x + tid; i < n4; i += stride) {
        float4 v = s4[i];
        // img255 first (f32), then *scale (f32) — bit-faithful to reference
        float t0 = v.x * 255.0f, t1 = v.y * 255.0f;
        float t2 = v.z * 255.0f, t3 = v.w * 255.0f;
        if (need_hist) {
            int i0 = min(max((int)(t0 * scale), 0), 255);
            int i1 = min(max((int)(t1 * scale), 0), 255);
            int i2 = min(max((int)(t2 * scale), 0), 255);
            int i3 = min(max((int)(t3 * scale), 0), 255);
            atomicAdd(&myh[i0], 1u);
            atomicAdd(&myh[i1], 1u);
            atomicAdd(&myh[i2], 1u);
            atomicAdd(&myh[i3], 1u);
        }
        if (is_dst) {
            // pix = clip(trunc(x*255), 0, 255)
            uchar4 p;
            p.x = (unsigned char)min(max((int)t0, 0), 255);
            p.y = (unsigned char)min(max((int)t1, 0), 255);
            p.z = (unsigned char)min(max((int)t2, 0), 255);
            p.w = (unsigned char)min(max((int)t3, 0), 255);
            p4[i] = p;
        }
    }

    if (need_hist) {
        __syncthreads();
        for (int i = tid; i < NBINS; i += blockDim.x) {
            unsigned int c = 0;
            #pragma unroll
            for (int w = 0; w < NWARP; w++) c += sh[w][i];
            if (c) atomicAdd(&g_hist[ch * NBINS + i], c);
        }
    }
}

// ---------------------------------------------------------------------------
// K2: per-channel CDFs + transfer table (used channels only).
// table[i] = first j in 1..255 with hr[j-1] <= hd[i] <= hr[j], else i;
// table[0]=0, table[255]=255. Stored pre-divided by 255.
// ---------------------------------------------------------------------------
__global__ void k_table() {
    const int k = blockIdx.x;
    if (!chan_used(k)) return;
    __shared__ float cd[NBINS];
    __shared__ float cr[NBINS];
    const int t = threadIdx.x;  // 256 threads

    // counts sum to exactly 2^20 -> normalization is an exact pow2 multiply
    cd[t] = (float)g_hist[k * NBINS + t] * (1.0f / 1048576.0f);
    cr[t] = (float)g_hist[(NCH + k) * NBINS + t] * (1.0f / 1048576.0f);
    __syncthreads();

    if (t == 0) {  // sequential f32 cumsum, same order as reference
        float a = 0.0f, b = 0.0f;
        for (int i = 0; i < NBINS; i++) {
            a += cd[i]; cd[i] = a;
            b += cr[i]; cr[i] = b;
        }
    }
    __syncthreads();

    int val = t;
    if (t > 0 && t < NBINS - 1) {
        const float x = cd[t];
        #pragma unroll 8
        for (int j = 1; j < NBINS; j++) {
            if (cr[j - 1] <= x && x <= cr[j]) { val = j; break; }
        }
    }
    g_table[k * NBINS + t] = (float)val / 255.0f;
}

// ---------------------------------------------------------------------------
// K3: gather. out = table[bugged_channel][pix] (already /255).
// Bug-faithful mapping: channel (b,c) uses table[b*c].
// ---------------------------------------------------------------------------
__global__ void k_gather(float* __restrict__ out) {
    const int ch = blockIdx.y;          // 0..23 (flat b*3+c)
    const int b = ch / 3, c = ch % 3;
    const int k = b * c;                // bug-faithful table index

    __shared__ float lut[NBINS];
    if (threadIdx.x < NBINS) lut[threadIdx.x] = g_table[k * NBINS + threadIdx.x];
    __syncthreads();

    const uchar4* __restrict__ p4 =
        reinterpret_cast<const uchar4*>(g_pix) + (size_t)ch * (CHPX / 4);
    float4* __restrict__ o4 =
        reinterpret_cast<float4*>(out) + (size_t)ch * (CHPX / 4);

    const int n4 = CHPX / 4;
    const int stride = gridDim.x * blockDim.x;
    for (int i = blockIdx.x * blockDim.x + threadIdx.x; i < n4; i += stride) {
        uchar4 p = p4[i];
        o4[i] = make_float4(lut[p.x], lut[p.y], lut[p.z], lut[p.w]);
    }
}

// ---------------------------------------------------------------------------
extern "C" void kernel_launch(void* const* d_in, const int* in_sizes, int n_in,
                              void* d_out, int out_size) {
    const float* dst = (const float*)d_in[0];
    const float* ref = (const float*)d_in[1];
    float* out = (float*)d_out;

    k_zero_hist<<<(2 * NCH * NBINS + 255) / 256, 256>>>();
    k_hist<<<dim3(64, 2 * NCH), 256>>>(dst, ref);
    k_table<<<NCH, NBINS>>>();
    k_gather<<<dim3(128, NCH), 256>>>(out);
}